// round 2
// baseline (speedup 1.0000x reference)
#include <cuda_runtime.h>
#include <cuda_bf16.h>
#include <math.h>

// Problem constants
#define BB 2
#define SS 2048
#define DD 1024
#define HH 16
#define HD 64
#define GM (BB*SS)   // 4096
#define GN DD        // 1024
#define GK DD        // 1024

// Scratch (device globals; no runtime allocation allowed)
__device__ float g_q[GM * DD];   // [B,H,S,HD]
__device__ float g_k[GM * DD];   // [B,H,S,HD]
__device__ float g_v[GM * DD];   // [B,H,S,HD]
__device__ float g_o[GM * DD];   // [B*S, D] attention output (pre-Wo)

// ---------------------------------------------------------------------------
// SGEMM: C[M,N] = A[M,K] @ W[K,N] + bias[N]
// BM=BN=128, BK=8, 256 threads, 8x8 register tile per thread.
// STORE_BHSD=1: scatter-store into [B,H,S,HD] layout for attention.
// ---------------------------------------------------------------------------
template<int STORE_BHSD>
__global__ __launch_bounds__(256)
void sgemm_bias(const float* __restrict__ A,
                const float* __restrict__ W,
                const float* __restrict__ bias,
                float* __restrict__ C)
{
    const int BM = 128, BN = 128, BK = 8;
    __shared__ float As[BK][BM];
    __shared__ float Bs[BK][BN];

    const int tid = threadIdx.x;
    const int bx = blockIdx.x;   // N tile (8)
    const int by = blockIdx.y;   // M tile (32)
    const int tx = tid % 16;
    const int ty = tid / 16;

    float acc[8][8];
#pragma unroll
    for (int i = 0; i < 8; ++i)
#pragma unroll
        for (int j = 0; j < 8; ++j) acc[i][j] = 0.f;

    const int arow = tid >> 1;         // 0..127
    const int acol = (tid & 1) * 4;    // 0 or 4
    const int brow = tid >> 5;         // 0..7
    const int bcol = (tid & 31) * 4;   // 0..124

    const float* Aptr = A + (size_t)(by * BM) * GK;
    const float* Wptr = W + bx * BN;

    for (int k0 = 0; k0 < GK; k0 += BK) {
        float4 av = *(const float4*)(Aptr + (size_t)arow * GK + k0 + acol);
        As[acol + 0][arow] = av.x;
        As[acol + 1][arow] = av.y;
        As[acol + 2][arow] = av.z;
        As[acol + 3][arow] = av.w;
        float4 bv = *(const float4*)(Wptr + (size_t)(k0 + brow) * GN + bcol);
        *(float4*)&Bs[brow][bcol] = bv;
        __syncthreads();

#pragma unroll
        for (int kk = 0; kk < BK; ++kk) {
            float4 a0 = *(const float4*)&As[kk][ty * 8];
            float4 a1 = *(const float4*)&As[kk][ty * 8 + 4];
            float4 b0 = *(const float4*)&Bs[kk][tx * 8];
            float4 b1 = *(const float4*)&Bs[kk][tx * 8 + 4];
            float a[8] = {a0.x, a0.y, a0.z, a0.w, a1.x, a1.y, a1.z, a1.w};
            float b[8] = {b0.x, b0.y, b0.z, b0.w, b1.x, b1.y, b1.z, b1.w};
#pragma unroll
            for (int i = 0; i < 8; ++i)
#pragma unroll
                for (int j = 0; j < 8; ++j)
                    acc[i][j] = fmaf(a[i], b[j], acc[i][j]);
        }
        __syncthreads();
    }

#pragma unroll
    for (int i = 0; i < 8; ++i) {
        const int m = by * BM + ty * 8 + i;
#pragma unroll
        for (int j = 0; j < 8; ++j) {
            const int n = bx * BN + tx * 8 + j;
            const float val = acc[i][j] + bias[n];
            if (STORE_BHSD) {
                const int b = m / SS, s = m % SS;
                const int h = n / HD, hd = n % HD;
                C[(((size_t)(b * HH + h)) * SS + s) * HD + hd] = val;
            } else {
                C[(size_t)m * GN + n] = val;
            }
        }
    }
}

// ---------------------------------------------------------------------------
// Flash attention with intervention mask.
// grid: (S/64, H, B), 256 threads (16x16), 4x4 register tile.
// Q tile 64x64, streamed K/V tiles of 64 keys; online softmax.
// SMEM: Qs[q][d], Kts[d][k], Vs[k][d], Ps[q][k], all stride 68; + mask vecs.
// Masks arrive as int32 (bool upcast by the harness).
// ---------------------------------------------------------------------------
#define FA_STRIDE 68
#define FA_SMEM ((4 * 64 * FA_STRIDE + 128) * 4)

__global__ __launch_bounds__(256)
void flash_attn(const int* __restrict__ cause_mask,
                const int* __restrict__ effect_mask,
                const float* __restrict__ strength_ptr)
{
    extern __shared__ float sm[];
    float* Qs  = sm;                       // [64][68]  q x d (pre-scaled)
    float* Kts = Qs  + 64 * FA_STRIDE;     // [64][68]  d x k (transposed)
    float* Vs  = Kts + 64 * FA_STRIDE;     // [64][68]  k x d
    float* Ps  = Vs  + 64 * FA_STRIDE;     // [64][68]  q x k
    float* cmv = Ps  + 64 * FA_STRIDE;     // [64]
    float* emv = cmv + 64;                 // [64]

    const int tid = threadIdx.x;
    const int tx = tid % 16;
    const int ty = tid / 16;
    const int b  = blockIdx.z;
    const int h  = blockIdx.y;
    const int q0 = blockIdx.x * 64;

    const float softscale = 0.125f;            // 1/sqrt(64)
    const float cfac = 0.5f * strength_ptr[0];

    const float* Qbase = g_q + (((size_t)(b * HH + h)) * SS + q0) * HD;

    // Load + pre-scale Q tile
    for (int i = tid; i < 64 * 64 / 4; i += 256) {
        const int r = i / 16;            // (i*4)/64
        const int c = (i % 16) * 4;      // (i*4)%64
        float4 v = *(const float4*)(Qbase + r * HD + c);
        v.x *= softscale; v.y *= softscale; v.z *= softscale; v.w *= softscale;
        *(float4*)&Qs[r * FA_STRIDE + c] = v;
    }
    if (tid < 64) cmv[tid] = (cause_mask[b * SS + q0 + tid] != 0) ? 1.f : 0.f;

    float mi[4], li[4], acc[4][4];
#pragma unroll
    for (int i = 0; i < 4; ++i) {
        mi[i] = -1e30f; li[i] = 0.f;
#pragma unroll
        for (int j = 0; j < 4; ++j) acc[i][j] = 0.f;
    }

    for (int kt = 0; kt < SS; kt += 64) {
        __syncthreads();  // previous tile's Ps/Vs reads done

        const float* Kbase = g_k + (((size_t)(b * HH + h)) * SS + kt) * HD;
        const float* Vbase = g_v + (((size_t)(b * HH + h)) * SS + kt) * HD;
        for (int i = tid; i < 64 * 64 / 4; i += 256) {
            const int r = i / 16;
            const int c = (i % 16) * 4;
            float4 kv4 = *(const float4*)(Kbase + r * HD + c);
            Kts[(c + 0) * FA_STRIDE + r] = kv4.x;
            Kts[(c + 1) * FA_STRIDE + r] = kv4.y;
            Kts[(c + 2) * FA_STRIDE + r] = kv4.z;
            Kts[(c + 3) * FA_STRIDE + r] = kv4.w;
            float4 vv4 = *(const float4*)(Vbase + r * HD + c);
            *(float4*)&Vs[r * FA_STRIDE + c] = vv4;
        }
        if (tid < 64) emv[tid] = (effect_mask[b * SS + kt + tid] != 0) ? 1.f : 0.f;
        __syncthreads();

        // S = Q @ K^T (Q pre-scaled)
        float s[4][4];
#pragma unroll
        for (int i = 0; i < 4; ++i)
#pragma unroll
            for (int j = 0; j < 4; ++j) s[i][j] = 0.f;

#pragma unroll 8
        for (int d = 0; d < 64; ++d) {
            float a[4];
#pragma unroll
            for (int i = 0; i < 4; ++i) a[i] = Qs[(ty * 4 + i) * FA_STRIDE + d];
            float4 bb = *(const float4*)&Kts[d * FA_STRIDE + tx * 4];
#pragma unroll
            for (int i = 0; i < 4; ++i) {
                s[i][0] = fmaf(a[i], bb.x, s[i][0]);
                s[i][1] = fmaf(a[i], bb.y, s[i][1]);
                s[i][2] = fmaf(a[i], bb.z, s[i][2]);
                s[i][3] = fmaf(a[i], bb.w, s[i][3]);
            }
        }

        // intervention mask: scores *= 1 - 0.5*strength*(cm&em)
        float em[4];
#pragma unroll
        for (int j = 0; j < 4; ++j) em[j] = emv[tx * 4 + j];
#pragma unroll
        for (int i = 0; i < 4; ++i) {
            const float cm = cmv[ty * 4 + i];
#pragma unroll
            for (int j = 0; j < 4; ++j)
                s[i][j] *= (1.f - cfac * cm * em[j]);
        }

        // online softmax update (rows span the 16 tx-lanes, aligned 16-lane groups)
#pragma unroll
        for (int i = 0; i < 4; ++i) {
            float rmax = fmaxf(fmaxf(s[i][0], s[i][1]), fmaxf(s[i][2], s[i][3]));
#pragma unroll
            for (int m = 1; m < 16; m <<= 1)
                rmax = fmaxf(rmax, __shfl_xor_sync(0xffffffffu, rmax, m));
            const float mnew = fmaxf(mi[i], rmax);
            const float alpha = __expf(mi[i] - mnew);
            mi[i] = mnew;
            float rsum = 0.f;
#pragma unroll
            for (int j = 0; j < 4; ++j) {
                const float p = __expf(s[i][j] - mnew);
                Ps[(ty * 4 + i) * FA_STRIDE + tx * 4 + j] = p;
                rsum += p;
            }
#pragma unroll
            for (int m = 1; m < 16; m <<= 1)
                rsum += __shfl_xor_sync(0xffffffffu, rsum, m);
            li[i] = li[i] * alpha + rsum;
#pragma unroll
            for (int j = 0; j < 4; ++j) acc[i][j] *= alpha;
        }
        __syncthreads();

        // O += P @ V
#pragma unroll 8
        for (int k = 0; k < 64; ++k) {
            float a[4];
#pragma unroll
            for (int i = 0; i < 4; ++i) a[i] = Ps[(ty * 4 + i) * FA_STRIDE + k];
            float4 bv = *(const float4*)&Vs[k * FA_STRIDE + tx * 4];
#pragma unroll
            for (int i = 0; i < 4; ++i) {
                acc[i][0] = fmaf(a[i], bv.x, acc[i][0]);
                acc[i][1] = fmaf(a[i], bv.y, acc[i][1]);
                acc[i][2] = fmaf(a[i], bv.z, acc[i][2]);
                acc[i][3] = fmaf(a[i], bv.w, acc[i][3]);
            }
        }
    }

    // write normalized output to g_o [B*S, D]
#pragma unroll
    for (int i = 0; i < 4; ++i) {
        const int q = q0 + ty * 4 + i;
        const float inv = 1.f / li[i];
        float* dst = g_o + ((size_t)(b * SS + q)) * DD + h * HD + tx * 4;
        float4 o;
        o.x = acc[i][0] * inv; o.y = acc[i][1] * inv;
        o.z = acc[i][2] * inv; o.w = acc[i][3] * inv;
        *(float4*)dst = o;
    }
}

// ---------------------------------------------------------------------------
extern "C" void kernel_launch(void* const* d_in, const int* in_sizes, int n_in,
                              void* d_out, int out_size)
{
    const float* x        = (const float*)d_in[0];
    const int*   cause    = (const int*)d_in[1];
    const int*   effect   = (const int*)d_in[2];
    const float* strength = (const float*)d_in[3];
    const float* Wq = (const float*)d_in[4];
    const float* bq = (const float*)d_in[5];
    const float* Wk = (const float*)d_in[6];
    const float* bk = (const float*)d_in[7];
    const float* Wv = (const float*)d_in[8];
    const float* bv = (const float*)d_in[9];
    const float* Wo = (const float*)d_in[10];
    const float* bo = (const float*)d_in[11];
    float* out = (float*)d_out;

    void *pq, *pk, *pv, *po;
    cudaGetSymbolAddress(&pq, g_q);
    cudaGetSymbolAddress(&pk, g_k);
    cudaGetSymbolAddress(&pv, g_v);
    cudaGetSymbolAddress(&po, g_o);

    static bool attr_set = false;
    if (!attr_set) {
        cudaFuncSetAttribute(flash_attn,
                             cudaFuncAttributeMaxDynamicSharedMemorySize, FA_SMEM);
        attr_set = true;
    }

    dim3 ggrid(GN / 128, GM / 128);   // (8, 32)

    sgemm_bias<1><<<ggrid, 256>>>(x, Wq, bq, (float*)pq);
    sgemm_bias<1><<<ggrid, 256>>>(x, Wk, bk, (float*)pk);
    sgemm_bias<1><<<ggrid, 256>>>(x, Wv, bv, (float*)pv);

    dim3 fgrid(SS / 64, HH, BB);      // (32, 16, 2)
    flash_attn<<<fgrid, 256, FA_SMEM>>>(cause, effect, strength);

    sgemm_bias<0><<<ggrid, 256>>>((const float*)po, Wo, bo, out);
}

// round 4
// speedup vs baseline: 2.4554x; 2.4554x over previous
#include <cuda_runtime.h>
#include <cuda_bf16.h>
#include <cstdint>

#define BB 2
#define SS 2048
#define DD 1024
#define HH 16
#define HD 64
#define GM (BB*SS)   // 4096
#define GN DD
#define GK DD

using bf16 = __nv_bfloat16;

// ---------------------------------------------------------------------------
// Device-global scratch (no runtime allocation allowed)
// ---------------------------------------------------------------------------
__device__ bf16 g_xhi[GM*DD], g_xlo[GM*DD];
__device__ bf16 g_wThi[4*DD*DD], g_wTlo[4*DD*DD];   // W^T [N,K] hi/lo
__device__ bf16 g_qhi[GM*DD], g_qlo[GM*DD];          // [B,H,S,HD], pre-scaled 1/8
__device__ bf16 g_khi[GM*DD], g_klo[GM*DD];
__device__ bf16 g_vhi[GM*DD], g_vlo[GM*DD];
__device__ bf16 g_ohi[GM*DD], g_olo[GM*DD];          // [B*S, D] attn out

// ---------------------------------------------------------------------------
// Helpers
// ---------------------------------------------------------------------------
__device__ __forceinline__ uint32_t smem_u32(const void* p) {
    uint32_t a;
    asm("{ .reg .u64 t; cvta.to.shared.u64 t, %1; cvt.u32.u64 %0, t; }"
        : "=r"(a) : "l"(p));
    return a;
}

// rows of 128B (8 x 16B chunks), XOR swizzle -> conflict-free ldmatrix
__device__ __forceinline__ uint32_t swz(uint32_t row, uint32_t cc) {
    return row * 128u + ((cc ^ (row & 7u)) << 4);
}

__device__ __forceinline__ void cp_async16(uint32_t s, const void* g) {
    asm volatile("cp.async.cg.shared.global [%0], [%1], 16;" :: "r"(s), "l"(g));
}
__device__ __forceinline__ void cp_async4(uint32_t s, const void* g) {
    asm volatile("cp.async.ca.shared.global [%0], [%1], 4;" :: "r"(s), "l"(g));
}
#define CP_COMMIT()  asm volatile("cp.async.commit_group;")
#define CP_WAIT1()   asm volatile("cp.async.wait_group 1;")
#define CP_WAIT0()   asm volatile("cp.async.wait_group 0;")

__device__ __forceinline__ void ldsm_x4(uint32_t* r, uint32_t a) {
    asm volatile("ldmatrix.sync.aligned.m8n8.x4.shared.b16 {%0,%1,%2,%3}, [%4];"
        : "=r"(r[0]), "=r"(r[1]), "=r"(r[2]), "=r"(r[3]) : "r"(a));
}
__device__ __forceinline__ void ldsm_x4_t(uint32_t* r, uint32_t a) {
    asm volatile("ldmatrix.sync.aligned.m8n8.x4.trans.shared.b16 {%0,%1,%2,%3}, [%4];"
        : "=r"(r[0]), "=r"(r[1]), "=r"(r[2]), "=r"(r[3]) : "r"(a));
}

__device__ __forceinline__ void mma_bf16(float* c, const uint32_t* a, const uint32_t* b) {
    asm volatile(
        "mma.sync.aligned.m16n8k16.row.col.f32.bf16.bf16.f32 "
        "{%0,%1,%2,%3}, {%4,%5,%6,%7}, {%8,%9}, {%0,%1,%2,%3};"
        : "+f"(c[0]), "+f"(c[1]), "+f"(c[2]), "+f"(c[3])
        : "r"(a[0]), "r"(a[1]), "r"(a[2]), "r"(a[3]), "r"(b[0]), "r"(b[1]));
}

__device__ __forceinline__ uint32_t bfpack(float a, float b) {
    __nv_bfloat162 h = __floats2bfloat162_rn(a, b);
    return *reinterpret_cast<uint32_t*>(&h);
}
__device__ __forceinline__ float2 bfunpack(uint32_t u) {
    __nv_bfloat162 h = *reinterpret_cast<__nv_bfloat162*>(&u);
    return __bfloat1622float2(h);
}

// ---------------------------------------------------------------------------
// Split fp32 -> bf16 hi/lo
// ---------------------------------------------------------------------------
__global__ __launch_bounds__(256)
void split_f32(const float* __restrict__ in,
               bf16* __restrict__ hi, bf16* __restrict__ lo)
{
    const int i = blockIdx.x * 256 + threadIdx.x;
    float4 v = ((const float4*)in)[i];
    uint32_t h01 = bfpack(v.x, v.y), h23 = bfpack(v.z, v.w);
    float2 f01 = bfunpack(h01), f23 = bfunpack(h23);
    uint32_t l01 = bfpack(v.x - f01.x, v.y - f01.y);
    uint32_t l23 = bfpack(v.z - f23.x, v.w - f23.y);
    ((uint32_t*)hi)[2*i]   = h01;  ((uint32_t*)hi)[2*i+1] = h23;
    ((uint32_t*)lo)[2*i]   = l01;  ((uint32_t*)lo)[2*i+1] = l23;
}

// W[K,N] fp32 -> W^T[N,K] bf16 hi/lo
__global__ __launch_bounds__(256)
void split_transpose(const float* __restrict__ W,
                     bf16* __restrict__ hiT, bf16* __restrict__ loT)
{
    __shared__ float t[32][33];
    const int tx = threadIdx.x, ty = threadIdx.y;   // 32 x 8
    const int n0 = blockIdx.x * 32, k0 = blockIdx.y * 32;
#pragma unroll
    for (int r = ty; r < 32; r += 8)
        t[r][tx] = W[(size_t)(k0 + r) * GN + n0 + tx];
    __syncthreads();
#pragma unroll
    for (int r = ty; r < 32; r += 8) {
        const float v = t[tx][r];
        const bf16 hv = __float2bfloat16(v);
        const bf16 lv = __float2bfloat16(v - __bfloat162float(hv));
        hiT[(size_t)(n0 + r) * GK + k0 + tx] = hv;
        loT[(size_t)(n0 + r) * GK + k0 + tx] = lv;
    }
}

// ---------------------------------------------------------------------------
// GEMM on mma.sync bf16 hi/lo 3-pass:  C[M,N] = A[M,K] @ W + bias
// A: hi/lo [M,K] row-major, B = W^T hi/lo [N,K].
// CTA 128x128, K-chunks of 64, cp.async double buffer, 8 warps (4Mx2N).
// MODE 0: fp32 C (+bias).   MODE 1: bf16 hi/lo, (acc+bias)*scale, BHSD scatter.
// ---------------------------------------------------------------------------
#define G_TILE  16384
#define G_STAGE (4*G_TILE)
#define G_SMEM  (2*G_STAGE)   // 128KB

template<int MODE>
__global__ __launch_bounds__(256)
void gemm_mma(const bf16* __restrict__ Ahi, const bf16* __restrict__ Alo,
              const bf16* __restrict__ Bhi, const bf16* __restrict__ Blo,
              const float* __restrict__ bias, float scale,
              float* __restrict__ C, bf16* __restrict__ Chi, bf16* __restrict__ Clo)
{
    extern __shared__ char smraw[];
    const uint32_t sb = smem_u32(smraw);
    const int tid = threadIdx.x, lane = tid & 31, warp = tid >> 5;
    const int wm = warp >> 1, wn = warp & 1;
    const int m0 = blockIdx.y * 128, n0 = blockIdx.x * 128;

    const int lrow = tid >> 1;
    const int lcc0 = (tid & 1) * 4;

    const bf16* gsrc[4];
    gsrc[0] = Ahi + (size_t)(m0 + lrow) * GK + lcc0 * 8;
    gsrc[1] = Alo + (size_t)(m0 + lrow) * GK + lcc0 * 8;
    gsrc[2] = Bhi + (size_t)(n0 + lrow) * GK + lcc0 * 8;
    gsrc[3] = Blo + (size_t)(n0 + lrow) * GK + lcc0 * 8;

    auto issue = [&](int stage) {
        const uint32_t buf = sb + (stage & 1) * G_STAGE;
#pragma unroll
        for (int t = 0; t < 4; ++t) {
            const bf16* g = gsrc[t] + stage * 64;
#pragma unroll
            for (int i = 0; i < 4; ++i)
                cp_async16(buf + t * G_TILE + swz(lrow, lcc0 + i), g + i * 8);
        }
        CP_COMMIT();
    };

    float c[2][8][4];
#pragma unroll
    for (int a = 0; a < 2; ++a)
#pragma unroll
        for (int b = 0; b < 8; ++b)
#pragma unroll
            for (int e = 0; e < 4; ++e) c[a][b][e] = 0.f;

    issue(0);
    for (int s = 0; s < 16; ++s) {
        if (s + 1 < 16) { issue(s + 1); CP_WAIT1(); } else { CP_WAIT0(); }
        __syncthreads();
        const uint32_t base = sb + (s & 1) * G_STAGE;
#pragma unroll
        for (int pass = 0; pass < 3; ++pass) {
            const uint32_t aT = base + ((pass == 2) ? G_TILE : 0);
            const uint32_t bT = base + 2 * G_TILE + ((pass == 1) ? G_TILE : 0);
#pragma unroll
            for (int kt = 0; kt < 4; ++kt) {
                uint32_t a0[4], a1[4];
                const uint32_t ar  = wm * 32 + (lane & 15);
                const uint32_t acc = kt * 2 + (lane >> 4);
                ldsm_x4(a0, aT + swz(ar, acc));
                ldsm_x4(a1, aT + swz(ar + 16, acc));
#pragma unroll
                for (int np = 0; np < 4; ++np) {
                    uint32_t bfr[4];
                    const uint32_t br  = wn * 64 + (2 * np + (lane >> 4)) * 8 + (lane & 7);
                    const uint32_t bcc = kt * 2 + ((lane >> 3) & 1);
                    ldsm_x4(bfr, bT + swz(br, bcc));
                    mma_bf16(c[0][2*np],   a0, bfr);
                    mma_bf16(c[0][2*np+1], a0, bfr + 2);
                    mma_bf16(c[1][2*np],   a1, bfr);
                    mma_bf16(c[1][2*np+1], a1, bfr + 2);
                }
            }
        }
        __syncthreads();
    }

#pragma unroll
    for (int mt = 0; mt < 2; ++mt) {
#pragma unroll
        for (int nt = 0; nt < 8; ++nt) {
            const int col = n0 + wn * 64 + nt * 8 + (lane & 3) * 2;
            const float2 bs = *(const float2*)(bias + col);
#pragma unroll
            for (int hf = 0; hf < 2; ++hf) {
                const int row = m0 + wm * 32 + mt * 16 + (lane >> 2) + hf * 8;
                float v0 = c[mt][nt][hf*2]     + bs.x;
                float v1 = c[mt][nt][hf*2 + 1] + bs.y;
                if (MODE == 0) {
                    *(float2*)(C + (size_t)row * GN + col) = make_float2(v0, v1);
                } else {
                    v0 *= scale; v1 *= scale;
                    const uint32_t hp = bfpack(v0, v1);
                    const float2 hfv = bfunpack(hp);
                    const uint32_t lp = bfpack(v0 - hfv.x, v1 - hfv.y);
                    const int bb = row >> 11, sq = row & 2047;
                    const int hh = col >> 6,  hd = col & 63;
                    const size_t off = (((size_t)(bb * HH + hh)) * SS + sq) * HD + hd;
                    *(uint32_t*)(Chi + off) = hp;
                    *(uint32_t*)(Clo + off) = lp;
                }
            }
        }
    }
}

// ---------------------------------------------------------------------------
// Flash attention on mma.sync. CTA: 128 Q rows x full keys (tiles of 64).
// 8 warps; warp w owns Q rows [16w,16w+16) for ALL keys (no x-warp reduce).
// S = Q K^T (3-pass hi/lo), online softmax, P reused in-register as A-frags
// for PV (3-pass, V via ldmatrix.trans). Writes bf16 hi/lo O.
// ---------------------------------------------------------------------------
#define F_QHI 0
#define F_QLO 16384
#define F_ST0 32768
#define F_STSZ 32768
#define F_KHI 0
#define F_KLO 8192
#define F_VHI 16384
#define F_VLO 24576
#define F_EMI (F_ST0 + 2*F_STSZ)
#define F_CMI (F_EMI + 512)
#define F_SMEM (F_CMI + 512)

__global__ __launch_bounds__(256)
void flash_mma(const int* __restrict__ cause, const int* __restrict__ effect,
               const float* __restrict__ strength)
{
    extern __shared__ char smraw[];
    const uint32_t sb = smem_u32(smraw);
    const int tid = threadIdx.x, lane = tid & 31, warp = tid >> 5;
    const int b = blockIdx.z, h = blockIdx.y, q0 = blockIdx.x * 128;
    const float cfac = 0.5f * strength[0];
    const float fm1 = 1.0f - cfac;

    const size_t headoff = ((size_t)(b * HH + h)) * SS;

    // prologue: Q hi/lo + cause mask (group 0 together with stage 0)
    {
        const bf16* qs[2] = { g_qhi + (headoff + q0) * HD,
                              g_qlo + (headoff + q0) * HD };
        const int r = tid >> 1, c0 = (tid & 1) * 4;
#pragma unroll
        for (int t = 0; t < 2; ++t)
#pragma unroll
            for (int i = 0; i < 4; ++i)
                cp_async16(sb + t * 16384 + swz(r, c0 + i),
                           qs[t] + (size_t)r * HD + (c0 + i) * 8);
        if (tid < 128) cp_async4(sb + F_CMI + tid * 4, cause + b * SS + q0 + tid);
    }

    auto issue = [&](int s) {
        const uint32_t st = sb + F_ST0 + (s & 1) * F_STSZ;
        const int kt0 = s * 64;
        const bf16* srcs[4] = { g_khi + (headoff + kt0) * HD,
                                g_klo + (headoff + kt0) * HD,
                                g_vhi + (headoff + kt0) * HD,
                                g_vlo + (headoff + kt0) * HD };
        const int r = tid >> 2, cc0 = (tid & 3) * 2;
#pragma unroll
        for (int t = 0; t < 4; ++t)
#pragma unroll
            for (int i = 0; i < 2; ++i)
                cp_async16(st + t * 8192 + swz(r, cc0 + i),
                           srcs[t] + (size_t)r * HD + (cc0 + i) * 8);
        if (tid < 64) cp_async4(sb + F_EMI + (s & 1) * 256 + tid * 4,
                                effect + b * SS + kt0 + tid);
        CP_COMMIT();
    };

    issue(0);

    float o[8][4];
#pragma unroll
    for (int i = 0; i < 8; ++i)
#pragma unroll
        for (int e = 0; e < 4; ++e) o[i][e] = 0.f;
    float mrow0 = -1e30f, mrow1 = -1e30f, lrow0 = 0.f, lrow1 = 0.f;
    uint32_t qh[4][4], ql[4][4];
    int cm0 = 0, cm1 = 0;

    for (int s = 0; s < 32; ++s) {
        if (s + 1 < 32) { issue(s + 1); CP_WAIT1(); } else { CP_WAIT0(); }
        __syncthreads();

        if (s == 0) {
            const uint32_t ar = warp * 16 + (lane & 15);
#pragma unroll
            for (int kt = 0; kt < 4; ++kt) {
                const uint32_t cc = kt * 2 + (lane >> 4);
                ldsm_x4(qh[kt], sb + F_QHI + swz(ar, cc));
                ldsm_x4(ql[kt], sb + F_QLO + swz(ar, cc));
            }
            const int* cmi = (const int*)(smraw + F_CMI);
            cm0 = cmi[warp * 16 + (lane >> 2)];
            cm1 = cmi[warp * 16 + (lane >> 2) + 8];
        }

        const uint32_t st = sb + F_ST0 + (s & 1) * F_STSZ;

        // ---- S = Q K^T
        float sc[8][4];
#pragma unroll
        for (int i = 0; i < 8; ++i)
#pragma unroll
            for (int e = 0; e < 4; ++e) sc[i][e] = 0.f;
#pragma unroll
        for (int pass = 0; pass < 3; ++pass) {
            uint32_t (*af)[4] = (pass == 2) ? ql : qh;
            const uint32_t bT = st + ((pass == 1) ? F_KLO : F_KHI);
#pragma unroll
            for (int kt = 0; kt < 4; ++kt) {
#pragma unroll
                for (int np = 0; np < 4; ++np) {
                    uint32_t bfr[4];
                    const uint32_t br  = (2 * np + (lane >> 4)) * 8 + (lane & 7);
                    const uint32_t bcc = kt * 2 + ((lane >> 3) & 1);
                    ldsm_x4(bfr, bT + swz(br, bcc));
                    mma_bf16(sc[2*np],   af[kt], bfr);
                    mma_bf16(sc[2*np+1], af[kt], bfr + 2);
                }
            }
        }

        // ---- intervention mask + online softmax
        const int* emi = (const int*)(smraw + F_EMI + (s & 1) * 256);
        float tm0 = -1e30f, tm1 = -1e30f;
#pragma unroll
        for (int nt = 0; nt < 8; ++nt) {
            const int col = nt * 8 + (lane & 3) * 2;
            const int e0 = emi[col], e1 = emi[col + 1];
            const float f00 = (cm0 && e0) ? fm1 : 1.0f;
            const float f01 = (cm0 && e1) ? fm1 : 1.0f;
            const float f10 = (cm1 && e0) ? fm1 : 1.0f;
            const float f11 = (cm1 && e1) ? fm1 : 1.0f;
            sc[nt][0] *= f00; sc[nt][1] *= f01;
            sc[nt][2] *= f10; sc[nt][3] *= f11;
            tm0 = fmaxf(tm0, fmaxf(sc[nt][0], sc[nt][1]));
            tm1 = fmaxf(tm1, fmaxf(sc[nt][2], sc[nt][3]));
        }
        tm0 = fmaxf(tm0, __shfl_xor_sync(0xffffffffu, tm0, 1));
        tm0 = fmaxf(tm0, __shfl_xor_sync(0xffffffffu, tm0, 2));
        tm1 = fmaxf(tm1, __shfl_xor_sync(0xffffffffu, tm1, 1));
        tm1 = fmaxf(tm1, __shfl_xor_sync(0xffffffffu, tm1, 2));
        const float mn0 = fmaxf(mrow0, tm0), mn1 = fmaxf(mrow1, tm1);
        const float al0 = __expf(mrow0 - mn0), al1 = __expf(mrow1 - mn1);
        mrow0 = mn0; mrow1 = mn1;

        float sum0 = 0.f, sum1 = 0.f;
        uint32_t pha[8], phb[8], pla[8], plb[8];
#pragma unroll
        for (int nt = 0; nt < 8; ++nt) {
            const float p0 = __expf(sc[nt][0] - mn0);
            const float p1 = __expf(sc[nt][1] - mn0);
            const float p2 = __expf(sc[nt][2] - mn1);
            const float p3 = __expf(sc[nt][3] - mn1);
            sum0 += p0 + p1; sum1 += p2 + p3;
            pha[nt] = bfpack(p0, p1);
            phb[nt] = bfpack(p2, p3);
            const float2 fa = bfunpack(pha[nt]);
            const float2 fb = bfunpack(phb[nt]);
            pla[nt] = bfpack(p0 - fa.x, p1 - fa.y);
            plb[nt] = bfpack(p2 - fb.x, p3 - fb.y);
        }
        sum0 += __shfl_xor_sync(0xffffffffu, sum0, 1);
        sum0 += __shfl_xor_sync(0xffffffffu, sum0, 2);
        sum1 += __shfl_xor_sync(0xffffffffu, sum1, 1);
        sum1 += __shfl_xor_sync(0xffffffffu, sum1, 2);
        lrow0 = lrow0 * al0 + sum0;
        lrow1 = lrow1 * al1 + sum1;
#pragma unroll
        for (int nt = 0; nt < 8; ++nt) {
            o[nt][0] *= al0; o[nt][1] *= al0;
            o[nt][2] *= al1; o[nt][3] *= al1;
        }

        // ---- O += P V   (P fragments straight from registers)
#pragma unroll
        for (int pass = 0; pass < 3; ++pass) {
            const uint32_t* pa = (pass == 2) ? pla : pha;
            const uint32_t* pb = (pass == 2) ? plb : phb;
            const uint32_t bT = st + ((pass == 1) ? F_VLO : F_VHI);
#pragma unroll
            for (int kt = 0; kt < 4; ++kt) {
                uint32_t a[4] = { pa[2*kt], pb[2*kt], pa[2*kt+1], pb[2*kt+1] };
#pragma unroll
                for (int np = 0; np < 4; ++np) {
                    uint32_t bfr[4];
                    const uint32_t vr  = kt * 16 + (((lane >> 3) & 1) << 3) + (lane & 7);
                    const uint32_t vcc = 2 * np + (lane >> 4);
                    ldsm_x4_t(bfr, bT + swz(vr, vcc));
                    mma_bf16(o[2*np],   a, bfr);
                    mma_bf16(o[2*np+1], a, bfr + 2);
                }
            }
        }
        __syncthreads();
    }

    // ---- epilogue: normalize, split hi/lo, store [B*S, D]
    const float inv0 = 1.0f / lrow0, inv1 = 1.0f / lrow1;
    const int row0 = b * SS + q0 + warp * 16 + (lane >> 2);
#pragma unroll
    for (int nt = 0; nt < 8; ++nt) {
        const int col = h * 64 + nt * 8 + (lane & 3) * 2;
        const float v0 = o[nt][0] * inv0, v1 = o[nt][1] * inv0;
        const float v2 = o[nt][2] * inv1, v3 = o[nt][3] * inv1;
        const uint32_t h0 = bfpack(v0, v1);
        const float2 f0 = bfunpack(h0);
        const uint32_t l0 = bfpack(v0 - f0.x, v1 - f0.y);
        const uint32_t h1 = bfpack(v2, v3);
        const float2 f1 = bfunpack(h1);
        const uint32_t l1 = bfpack(v2 - f1.x, v3 - f1.y);
        *(uint32_t*)(g_ohi + (size_t)row0 * DD + col)       = h0;
        *(uint32_t*)(g_olo + (size_t)row0 * DD + col)       = l0;
        *(uint32_t*)(g_ohi + (size_t)(row0 + 8) * DD + col) = h1;
        *(uint32_t*)(g_olo + (size_t)(row0 + 8) * DD + col) = l1;
    }
}

// ---------------------------------------------------------------------------
extern "C" void kernel_launch(void* const* d_in, const int* in_sizes, int n_in,
                              void* d_out, int out_size)
{
    const float* x        = (const float*)d_in[0];
    const int*   cause    = (const int*)d_in[1];
    const int*   effect   = (const int*)d_in[2];
    const float* strength = (const float*)d_in[3];
    const float* Wq = (const float*)d_in[4];
    const float* bq = (const float*)d_in[5];
    const float* Wk = (const float*)d_in[6];
    const float* bk = (const float*)d_in[7];
    const float* Wv = (const float*)d_in[8];
    const float* bv = (const float*)d_in[9];
    const float* Wo = (const float*)d_in[10];
    const float* bo = (const float*)d_in[11];
    float* out = (float*)d_out;

    void *pxhi, *pxlo, *pwhi, *pwlo;
    void *pqhi, *pqlo, *pkhi, *pklo, *pvhi, *pvlo, *pohi, *polo;
    cudaGetSymbolAddress(&pxhi, g_xhi);  cudaGetSymbolAddress(&pxlo, g_xlo);
    cudaGetSymbolAddress(&pwhi, g_wThi); cudaGetSymbolAddress(&pwlo, g_wTlo);
    cudaGetSymbolAddress(&pqhi, g_qhi);  cudaGetSymbolAddress(&pqlo, g_qlo);
    cudaGetSymbolAddress(&pkhi, g_khi);  cudaGetSymbolAddress(&pklo, g_klo);
    cudaGetSymbolAddress(&pvhi, g_vhi);  cudaGetSymbolAddress(&pvlo, g_vlo);
    cudaGetSymbolAddress(&pohi, g_ohi);  cudaGetSymbolAddress(&polo, g_olo);

    bf16* xhi = (bf16*)pxhi; bf16* xlo = (bf16*)pxlo;
    bf16* whi = (bf16*)pwhi; bf16* wlo = (bf16*)pwlo;

    static bool attr_set = false;
    if (!attr_set) {
        cudaFuncSetAttribute(gemm_mma<0>, cudaFuncAttributeMaxDynamicSharedMemorySize, G_SMEM);
        cudaFuncSetAttribute(gemm_mma<1>, cudaFuncAttributeMaxDynamicSharedMemorySize, G_SMEM);
        cudaFuncSetAttribute(flash_mma,   cudaFuncAttributeMaxDynamicSharedMemorySize, F_SMEM);
        attr_set = true;
    }

    // splits
    split_f32<<<GM * DD / 4 / 256, 256>>>(x, xhi, xlo);
    dim3 tgrid(32, 32), tblk(32, 8);
    const float* Ws[4] = {Wq, Wk, Wv, Wo};
    for (int w = 0; w < 4; ++w)
        split_transpose<<<tgrid, tblk>>>(Ws[w], whi + (size_t)w * DD * DD,
                                                wlo + (size_t)w * DD * DD);

    // QKV projections (Q pre-scaled by 1/sqrt(HD))
    dim3 ggrid(GN / 128, GM / 128);   // (8, 32)
    gemm_mma<1><<<ggrid, 256, G_SMEM>>>(xhi, xlo, whi + 0*(size_t)DD*DD, wlo + 0*(size_t)DD*DD,
                                        bq, 0.125f, nullptr, (bf16*)pqhi, (bf16*)pqlo);
    gemm_mma<1><<<ggrid, 256, G_SMEM>>>(xhi, xlo, whi + 1*(size_t)DD*DD, wlo + 1*(size_t)DD*DD,
                                        bk, 1.0f,   nullptr, (bf16*)pkhi, (bf16*)pklo);
    gemm_mma<1><<<ggrid, 256, G_SMEM>>>(xhi, xlo, whi + 2*(size_t)DD*DD, wlo + 2*(size_t)DD*DD,
                                        bv, 1.0f,   nullptr, (bf16*)pvhi, (bf16*)pvlo);

    // attention
    dim3 fgrid(SS / 128, HH, BB);     // (16, 16, 2)
    flash_mma<<<fgrid, 256, F_SMEM>>>(cause, effect, strength);

    // output projection
    gemm_mma<0><<<ggrid, 256, G_SMEM>>>((bf16*)pohi, (bf16*)polo,
                                        whi + 3*(size_t)DD*DD, wlo + 3*(size_t)DD*DD,
                                        bo, 1.0f, out, nullptr, nullptr);
}